// round 3
// baseline (speedup 1.0000x reference)
#include <cuda_runtime.h>
#include <math.h>

#define Bx 8
#define Nx 1024
#define Cx 64
#define Ox 64
#define Mx 4                 // K+1
#define BN (Bx*Nx)           // 8192
#define BNO (BN*Ox)          // 524288

// ---------------- scratch (device globals; no allocations allowed) ----------
__device__ float g_sRi[BN], g_sIi[BN], g_sRj[BN], g_sIj[BN];
__device__ float g_cmax[BN], g_rsum[BN];
__device__ float g_rowR[Bx*Mx*Nx], g_rowI[Bx*Mx*Nx];

// ---------------- kernel A: attention projections ---------------------------
__global__ void __launch_bounds__(256) kA(const float* __restrict__ Xr,
                                          const float* __restrict__ Xi,
                                          const float* __restrict__ awr,
                                          const float* __restrict__ awi)
{
    int gw   = (blockIdx.x * blockDim.x + threadIdx.x) >> 5;
    int lane = threadIdx.x & 31;
    if (gw >= BN) return;
    const float* xr = Xr + (size_t)gw * Cx;
    const float* xi = Xi + (size_t)gw * Cx;
    float a1=0.f,a2=0.f,a3=0.f,a4=0.f,a5=0.f,a6=0.f,a7=0.f,a8=0.f;
#pragma unroll
    for (int k = 0; k < 2; k++) {
        int c = lane + (k << 5);
        float xrv = xr[c], xiv = xi[c];
        float wri = awr[c],      wii = awi[c];
        float wrj = awr[Cx + c], wij = awi[Cx + c];
        a1 = fmaf(xrv, wri, a1);  a2 = fmaf(xiv, wii, a2);
        a3 = fmaf(xrv, wii, a3);  a4 = fmaf(xiv, wri, a4);
        a5 = fmaf(xrv, wrj, a5);  a6 = fmaf(xiv, wij, a6);
        a7 = fmaf(xrv, wij, a7);  a8 = fmaf(xiv, wrj, a8);
    }
#pragma unroll
    for (int off = 16; off; off >>= 1) {
        a1 += __shfl_xor_sync(0xffffffffu, a1, off);
        a2 += __shfl_xor_sync(0xffffffffu, a2, off);
        a3 += __shfl_xor_sync(0xffffffffu, a3, off);
        a4 += __shfl_xor_sync(0xffffffffu, a4, off);
        a5 += __shfl_xor_sync(0xffffffffu, a5, off);
        a6 += __shfl_xor_sync(0xffffffffu, a6, off);
        a7 += __shfl_xor_sync(0xffffffffu, a7, off);
        a8 += __shfl_xor_sync(0xffffffffu, a8, off);
    }
    if (lane == 0) {
        g_sRi[gw] = a1 - a2;
        g_sIi[gw] = a3 + a4;
        g_sRj[gw] = a5 - a6;
        g_sIj[gw] = a7 + a8;
    }
}

// ---------------- kernel B: per-(b,j) softmax stats over i ------------------
__global__ void __launch_bounds__(256) kB(const float* __restrict__ br,
                                          const float* __restrict__ bi,
                                          const float* __restrict__ par,
                                          const float* __restrict__ pai)
{
    __shared__ float sri_s[Nx], sii_s[Nx];
    __shared__ float red[8];
    int b  = blockIdx.x >> 8;
    int j0 = (blockIdx.x & 255) << 2;
    float biasr = br[0], biasi = bi[0];
    float apr = par[0], api = pai[0];
    for (int t = threadIdx.x; t < Nx; t += 256) {
        sri_s[t] = g_sRi[b*Nx + t] + biasr;
        sii_s[t] = g_sIi[b*Nx + t] + biasi;
    }
    __syncthreads();
    int lane = threadIdx.x & 31, wid = threadIdx.x >> 5;
    for (int jj = 0; jj < 4; jj++) {
        int j = j0 + jj;
        float sjr = g_sRj[b*Nx + j];
        float sji = g_sIj[b*Nx + j];
        float mags[4];
        float lmax = -1e30f;
#pragma unroll
        for (int k = 0; k < 4; k++) {
            int i = threadIdx.x + (k << 8);
            float scr = sri_s[i] + sjr;
            float sci = sii_s[i] + sji;
            float pr = scr >= 0.f ? scr : apr * scr;
            float pi = sci >= 0.f ? sci : api * sci;
            float s2 = fmaf(pr, pr, pi * pi);
            float rm = rsqrtf(fmaxf(s2, 1e-36f));
            float mg = s2 * rm;
            mags[k] = mg;
            lmax = fmaxf(lmax, mg);
        }
#pragma unroll
        for (int off = 16; off; off >>= 1)
            lmax = fmaxf(lmax, __shfl_xor_sync(0xffffffffu, lmax, off));
        if (lane == 0) red[wid] = lmax;
        __syncthreads();
        float M = red[0];
#pragma unroll
        for (int t = 1; t < 8; t++) M = fmaxf(M, red[t]);
        __syncthreads();
        float ls = 0.f;
#pragma unroll
        for (int k = 0; k < 4; k++) ls += __expf(mags[k] - M);
#pragma unroll
        for (int off = 16; off; off >>= 1)
            ls += __shfl_xor_sync(0xffffffffu, ls, off);
        if (lane == 0) red[wid] = ls;
        __syncthreads();
        if (threadIdx.x == 0) {
            float S = red[0]+red[1]+red[2]+red[3]+red[4]+red[5]+red[6]+red[7];
            g_cmax[b*Nx + j] = M;
            g_rsum[b*Nx + j] = 1.0f / S;
        }
        __syncthreads();
    }
}

// ---------------- kernel C v2: 268 MB L reduction, float4 streams -----------
// grid: 8*128 blocks, 8 warps/block, one warp per i-row.
// Each lane handles 4 consecutive j via float4 from all 8 streams (4m x r/i):
// 8 LDG.128 front-batched per step -> deep MLP, 4x fewer load instructions.
__global__ void __launch_bounds__(256) kC(const float* __restrict__ Lr,
                                          const float* __restrict__ Li,
                                          const float* __restrict__ br,
                                          const float* __restrict__ bi,
                                          const float* __restrict__ par,
                                          const float* __restrict__ pai)
{
    __shared__ float sjr_s[Nx], sji_s[Nx], cm_s[Nx], rs_s[Nx];
    int b  = blockIdx.x >> 7;
    int i0 = (blockIdx.x & 127) << 3;
    for (int t = threadIdx.x; t < Nx; t += 256) {
        sjr_s[t] = g_sRj[b*Nx + t];
        sji_s[t] = g_sIj[b*Nx + t];
        cm_s[t]  = g_cmax[b*Nx + t];
        rs_s[t]  = g_rsum[b*Nx + t];
    }
    __syncthreads();
    int wid = threadIdx.x >> 5, lane = threadIdx.x & 31;
    int i = i0 + wid;
    float sri = g_sRi[b*Nx + i] + br[0];
    float sii = g_sIi[b*Nx + i] + bi[0];
    float apr = par[0], api = pai[0];
    const size_t MS = (size_t)Nx * Nx;
    const float* pR = Lr + (size_t)b * Mx * MS + (size_t)i * Nx;
    const float* pI = Li + (size_t)b * Mx * MS + (size_t)i * Nx;

    float aR[4] = {0.f,0.f,0.f,0.f};
    float aI[4] = {0.f,0.f,0.f,0.f};

#pragma unroll 1
    for (int jb = 0; jb < Nx; jb += 128) {
        int j0 = jb + (lane << 2);
        // front-batch all 8 stream loads (LDG.128, streaming)
        float4 R0 = __ldcs((const float4*)(pR          + j0));
        float4 R1 = __ldcs((const float4*)(pR +   MS   + j0));
        float4 R2 = __ldcs((const float4*)(pR + 2*MS   + j0));
        float4 R3 = __ldcs((const float4*)(pR + 3*MS   + j0));
        float4 I0 = __ldcs((const float4*)(pI          + j0));
        float4 I1 = __ldcs((const float4*)(pI +   MS   + j0));
        float4 I2 = __ldcs((const float4*)(pI + 2*MS   + j0));
        float4 I3 = __ldcs((const float4*)(pI + 3*MS   + j0));
        float4 vjr = *(const float4*)&sjr_s[j0];
        float4 vji = *(const float4*)&sji_s[j0];
        float4 vcm = *(const float4*)&cm_s[j0];
        float4 vrs = *(const float4*)&rs_s[j0];

        float ar[4], ai[4];
        const float* jr = (const float*)&vjr;
        const float* ji = (const float*)&vji;
        const float* cm = (const float*)&vcm;
        const float* rs = (const float*)&vrs;
#pragma unroll
        for (int q = 0; q < 4; q++) {
            float scr = sri + jr[q];
            float sci = sii + ji[q];
            float pr = scr >= 0.f ? scr : apr * scr;
            float pi = sci >= 0.f ? sci : api * sci;
            float s2 = fmaf(pr, pr, pi * pi);
            float rm = rsqrtf(fmaxf(s2, 1e-36f));
            float mg = s2 * rm;
            float sc = __fdividef(__expf(mg - cm[q]) * rs[q], mg + 1e-12f);
            ar[q] = sc * pr;
            ai[q] = sc * pi;
        }
        const float* r0 = (const float*)&R0; const float* i0p = (const float*)&I0;
        const float* r1 = (const float*)&R1; const float* i1p = (const float*)&I1;
        const float* r2 = (const float*)&R2; const float* i2p = (const float*)&I2;
        const float* r3 = (const float*)&R3; const float* i3p = (const float*)&I3;
#pragma unroll
        for (int q = 0; q < 4; q++) {
            aR[0] = fmaf(r0[q], ar[q], fmaf(i0p[q], -ai[q], aR[0]));
            aI[0] = fmaf(r0[q], ai[q], fmaf(i0p[q],  ar[q], aI[0]));
            aR[1] = fmaf(r1[q], ar[q], fmaf(i1p[q], -ai[q], aR[1]));
            aI[1] = fmaf(r1[q], ai[q], fmaf(i1p[q],  ar[q], aI[1]));
            aR[2] = fmaf(r2[q], ar[q], fmaf(i2p[q], -ai[q], aR[2]));
            aI[2] = fmaf(r2[q], ai[q], fmaf(i2p[q],  ar[q], aI[2]));
            aR[3] = fmaf(r3[q], ar[q], fmaf(i3p[q], -ai[q], aR[3]));
            aI[3] = fmaf(r3[q], ai[q], fmaf(i3p[q],  ar[q], aI[3]));
        }
    }
#pragma unroll
    for (int off = 16; off; off >>= 1) {
#pragma unroll
        for (int m = 0; m < 4; m++) {
            aR[m] += __shfl_xor_sync(0xffffffffu, aR[m], off);
            aI[m] += __shfl_xor_sync(0xffffffffu, aI[m], off);
        }
    }
    if (lane == 0) {
        size_t o = (size_t)b * Mx * Nx + i;
#pragma unroll
        for (int m = 0; m < 4; m++) {
            g_rowR[o + m*Nx] = aR[m];
            g_rowI[o + m*Nx] = aI[m];
        }
    }
}

// ---------------- kernel D v3: fused output GEMM, 512 blocks ----------------
// Block: 16 rows x 64 outputs, 256 threads (ty=row 0..15, tx=4 outputs).
// SMEM: X tile transposed [c][r] (stride 17), weights per-m [c][o] stride 68.
// ~44KB dyn smem -> 3-4 blocks/SM co-resident -> ~28 warps/SM.
__global__ void __launch_bounds__(256) kD(const float* __restrict__ Xr,
                                          const float* __restrict__ Xi,
                                          const float* __restrict__ wr,
                                          const float* __restrict__ wi,
                                          float* __restrict__ out)
{
    extern __shared__ __align__(16) float sm[];
    float* Xr_s = sm;                  // [64][17]
    float* Xi_s = sm + 64*17;          // [64][17]
    float* wr_s = sm + 2*64*17;        // [64][68]
    float* wi_s = sm + 2*64*17 + 64*68;// [64][68]

    int tid = threadIdx.x;
    int r0 = blockIdx.x << 4;          // 16 rows per block
    int b  = r0 >> 10;
    int jbase = r0 & 1023;

    // stage X tile transposed: 256 threads, each one (row, 4-channel group)
    {
        int r  = tid >> 4;             // 0..15
        int cg = (tid & 15) << 2;      // 0..60
        float4 v = __ldg((const float4*)(Xr + (size_t)(r0 + r)*64 + cg));
        Xr_s[(cg+0)*17 + r] = v.x;
        Xr_s[(cg+1)*17 + r] = v.y;
        Xr_s[(cg+2)*17 + r] = v.z;
        Xr_s[(cg+3)*17 + r] = v.w;
        float4 u = __ldg((const float4*)(Xi + (size_t)(r0 + r)*64 + cg));
        Xi_s[(cg+0)*17 + r] = u.x;
        Xi_s[(cg+1)*17 + r] = u.y;
        Xi_s[(cg+2)*17 + r] = u.z;
        Xi_s[(cg+3)*17 + r] = u.w;
    }

    int tx = tid & 15, ty = tid >> 4;  // ty = local row, tx*4 = output base
    int oo = tx << 2;

    // combine scalars for this row, all 4 m
    float cR[Mx], cI[Mx];
#pragma unroll
    for (int m = 0; m < Mx; m++) {
        size_t o = (size_t)(b*Mx + m)*Nx + jbase + ty;
        cR[m] = g_rowR[o];
        cI[m] = g_rowI[o];
    }

    float aR[4] = {0.f,0.f,0.f,0.f};
    float aI[4] = {0.f,0.f,0.f,0.f};

#pragma unroll 1
    for (int m = 0; m < Mx; m++) {
        __syncthreads();               // previous phase done reading w_s
        {
            const float4* wrg = (const float4*)(wr + (size_t)m * 4096);
            const float4* wig = (const float4*)(wi + (size_t)m * 4096);
#pragma unroll
            for (int k = 0; k < 4; k++) {
                int idx = tid + (k << 8);      // 0..1023
                int c = idx >> 4, og = (idx & 15) << 2;
                *(float4*)&wr_s[c*68 + og] = __ldg(wrg + idx);
                *(float4*)&wi_s[c*68 + og] = __ldg(wig + idx);
            }
        }
        __syncthreads();

        float pR[4] = {0.f,0.f,0.f,0.f};
        float pI[4] = {0.f,0.f,0.f,0.f};
#pragma unroll 8
        for (int c = 0; c < 64; c++) {
            float xrv = Xr_s[c*17 + ty];        // broadcast within half-warp
            float xiv = Xi_s[c*17 + ty];
            float4 wv = *(const float4*)&wr_s[c*68 + oo];
            float4 vv = *(const float4*)&wi_s[c*68 + oo];
            pR[0] = fmaf(xrv, wv.x, pR[0]);
            pR[1] = fmaf(xrv, wv.y, pR[1]);
            pR[2] = fmaf(xrv, wv.z, pR[2]);
            pR[3] = fmaf(xrv, wv.w, pR[3]);
            pI[0] = fmaf(xiv, vv.x, pI[0]);
            pI[1] = fmaf(xiv, vv.y, pI[1]);
            pI[2] = fmaf(xiv, vv.z, pI[2]);
            pI[3] = fmaf(xiv, vv.w, pI[3]);
        }
#pragma unroll
        for (int o = 0; o < 4; o++) {
            aR[o] = fmaf(cR[m], pR[o], fmaf(-cI[m], pI[o], aR[o]));
            aI[o] = fmaf(cI[m], pR[o], fmaf( cR[m], pI[o], aI[o]));
        }
    }

    {
        size_t row = (size_t)(r0 + ty);
        float4 vr = make_float4(aR[0], aR[1], aR[2], aR[3]);
        float4 vi = make_float4(aI[0], aI[1], aI[2], aI[3]);
        *(float4*)(out + row*64 + oo)               = vr;   // real block
        *(float4*)(out + (size_t)BNO + row*64 + oo) = vi;   // imag block
    }
}

// ---------------- launch ----------------------------------------------------
extern "C" void kernel_launch(void* const* d_in, const int* in_sizes, int n_in,
                              void* d_out, int out_size)
{
    const float* Xr  = (const float*)d_in[0];
    const float* Xi  = (const float*)d_in[1];
    const float* Lr  = (const float*)d_in[2];
    const float* Li  = (const float*)d_in[3];
    const float* wr  = (const float*)d_in[4];
    const float* wi  = (const float*)d_in[5];
    const float* awr = (const float*)d_in[6];
    const float* awi = (const float*)d_in[7];
    const float* abr = (const float*)d_in[8];
    const float* abi = (const float*)d_in[9];
    const float* par = (const float*)d_in[10];
    const float* pai = (const float*)d_in[11];
    float* out = (float*)d_out;

    const int KD_SMEM = (2*64*17 + 2*64*68) * 4;   // 43520 bytes
    static int attr_done = 0;
    if (!attr_done) {
        cudaFuncSetAttribute(kD, cudaFuncAttributeMaxDynamicSharedMemorySize, KD_SMEM);
        attr_done = 1;
    }

    kA<<<BN/8, 256>>>(Xr, Xi, awr, awi);
    kB<<<Bx*256, 256>>>(abr, abi, par, pai);
    kC<<<Bx*128, 256>>>(Lr, Li, abr, abi, par, pai);
    kD<<<BN/16, 256, KD_SMEM>>>(Xr, Xi, wr, wi, out);
}

// round 4
// speedup vs baseline: 1.2987x; 1.2987x over previous
#include <cuda_runtime.h>
#include <math.h>

#define Bx 8
#define Nx 1024
#define Cx 64
#define Ox 64
#define Mx 4                 // K+1
#define BN (Bx*Nx)           // 8192
#define BNO (BN*Ox)          // 524288

// ---------------- scratch (device globals; no allocations allowed) ----------
__device__ float g_sRi[BN], g_sIi[BN], g_sRj[BN], g_sIj[BN];
__device__ float g_cmax[BN], g_rsum[BN];
__device__ float g_rowR[Bx*Mx*Nx], g_rowI[Bx*Mx*Nx];

// ---------------- kernel A: attention projections ---------------------------
__global__ void __launch_bounds__(256) kA(const float* __restrict__ Xr,
                                          const float* __restrict__ Xi,
                                          const float* __restrict__ awr,
                                          const float* __restrict__ awi)
{
    int gw   = (blockIdx.x * blockDim.x + threadIdx.x) >> 5;
    int lane = threadIdx.x & 31;
    if (gw >= BN) return;
    const float* xr = Xr + (size_t)gw * Cx;
    const float* xi = Xi + (size_t)gw * Cx;
    float a1=0.f,a2=0.f,a3=0.f,a4=0.f,a5=0.f,a6=0.f,a7=0.f,a8=0.f;
#pragma unroll
    for (int k = 0; k < 2; k++) {
        int c = lane + (k << 5);
        float xrv = xr[c], xiv = xi[c];
        float wri = awr[c],      wii = awi[c];
        float wrj = awr[Cx + c], wij = awi[Cx + c];
        a1 = fmaf(xrv, wri, a1);  a2 = fmaf(xiv, wii, a2);
        a3 = fmaf(xrv, wii, a3);  a4 = fmaf(xiv, wri, a4);
        a5 = fmaf(xrv, wrj, a5);  a6 = fmaf(xiv, wij, a6);
        a7 = fmaf(xrv, wij, a7);  a8 = fmaf(xiv, wrj, a8);
    }
#pragma unroll
    for (int off = 16; off; off >>= 1) {
        a1 += __shfl_xor_sync(0xffffffffu, a1, off);
        a2 += __shfl_xor_sync(0xffffffffu, a2, off);
        a3 += __shfl_xor_sync(0xffffffffu, a3, off);
        a4 += __shfl_xor_sync(0xffffffffu, a4, off);
        a5 += __shfl_xor_sync(0xffffffffu, a5, off);
        a6 += __shfl_xor_sync(0xffffffffu, a6, off);
        a7 += __shfl_xor_sync(0xffffffffu, a7, off);
        a8 += __shfl_xor_sync(0xffffffffu, a8, off);
    }
    if (lane == 0) {
        g_sRi[gw] = a1 - a2;
        g_sIi[gw] = a3 + a4;
        g_sRj[gw] = a5 - a6;
        g_sIj[gw] = a7 + a8;
    }
}

// ---------------- kernel B: per-(b,j) softmax stats over i ------------------
__global__ void __launch_bounds__(256) kB(const float* __restrict__ br,
                                          const float* __restrict__ bi,
                                          const float* __restrict__ par,
                                          const float* __restrict__ pai)
{
    __shared__ float sri_s[Nx], sii_s[Nx];
    __shared__ float red[8];
    int b  = blockIdx.x >> 8;
    int j0 = (blockIdx.x & 255) << 2;
    float biasr = br[0], biasi = bi[0];
    float apr = par[0], api = pai[0];
    for (int t = threadIdx.x; t < Nx; t += 256) {
        sri_s[t] = g_sRi[b*Nx + t] + biasr;
        sii_s[t] = g_sIi[b*Nx + t] + biasi;
    }
    __syncthreads();
    int lane = threadIdx.x & 31, wid = threadIdx.x >> 5;
    for (int jj = 0; jj < 4; jj++) {
        int j = j0 + jj;
        float sjr = g_sRj[b*Nx + j];
        float sji = g_sIj[b*Nx + j];
        float mags[4];
        float lmax = -1e30f;
#pragma unroll
        for (int k = 0; k < 4; k++) {
            int i = threadIdx.x + (k << 8);
            float scr = sri_s[i] + sjr;
            float sci = sii_s[i] + sji;
            float pr = scr >= 0.f ? scr : apr * scr;
            float pi = sci >= 0.f ? sci : api * sci;
            float s2 = fmaf(pr, pr, pi * pi);
            float rm = rsqrtf(fmaxf(s2, 1e-36f));
            float mg = s2 * rm;
            mags[k] = mg;
            lmax = fmaxf(lmax, mg);
        }
#pragma unroll
        for (int off = 16; off; off >>= 1)
            lmax = fmaxf(lmax, __shfl_xor_sync(0xffffffffu, lmax, off));
        if (lane == 0) red[wid] = lmax;
        __syncthreads();
        float M = red[0];
#pragma unroll
        for (int t = 1; t < 8; t++) M = fmaxf(M, red[t]);
        __syncthreads();
        float ls = 0.f;
#pragma unroll
        for (int k = 0; k < 4; k++) ls += __expf(mags[k] - M);
#pragma unroll
        for (int off = 16; off; off >>= 1)
            ls += __shfl_xor_sync(0xffffffffu, ls, off);
        if (lane == 0) red[wid] = ls;
        __syncthreads();
        if (threadIdx.x == 0) {
            float S = red[0]+red[1]+red[2]+red[3]+red[4]+red[5]+red[6]+red[7];
            g_cmax[b*Nx + j] = M;
            g_rsum[b*Nx + j] = 1.0f / S;
        }
        __syncthreads();
    }
}

// ---------------- kernel C v2: 268 MB L reduction, float4 streams -----------
__global__ void __launch_bounds__(256) kC(const float* __restrict__ Lr,
                                          const float* __restrict__ Li,
                                          const float* __restrict__ br,
                                          const float* __restrict__ bi,
                                          const float* __restrict__ par,
                                          const float* __restrict__ pai)
{
    __shared__ float sjr_s[Nx], sji_s[Nx], cm_s[Nx], rs_s[Nx];
    int b  = blockIdx.x >> 7;
    int i0 = (blockIdx.x & 127) << 3;
    for (int t = threadIdx.x; t < Nx; t += 256) {
        sjr_s[t] = g_sRj[b*Nx + t];
        sji_s[t] = g_sIj[b*Nx + t];
        cm_s[t]  = g_cmax[b*Nx + t];
        rs_s[t]  = g_rsum[b*Nx + t];
    }
    __syncthreads();
    int wid = threadIdx.x >> 5, lane = threadIdx.x & 31;
    int i = i0 + wid;
    float sri = g_sRi[b*Nx + i] + br[0];
    float sii = g_sIi[b*Nx + i] + bi[0];
    float apr = par[0], api = pai[0];
    const size_t MS = (size_t)Nx * Nx;
    const float* pR = Lr + (size_t)b * Mx * MS + (size_t)i * Nx;
    const float* pI = Li + (size_t)b * Mx * MS + (size_t)i * Nx;

    float aR[4] = {0.f,0.f,0.f,0.f};
    float aI[4] = {0.f,0.f,0.f,0.f};

#pragma unroll 1
    for (int jb = 0; jb < Nx; jb += 128) {
        int j0 = jb + (lane << 2);
        float4 R0 = __ldcs((const float4*)(pR          + j0));
        float4 R1 = __ldcs((const float4*)(pR +   MS   + j0));
        float4 R2 = __ldcs((const float4*)(pR + 2*MS   + j0));
        float4 R3 = __ldcs((const float4*)(pR + 3*MS   + j0));
        float4 I0 = __ldcs((const float4*)(pI          + j0));
        float4 I1 = __ldcs((const float4*)(pI +   MS   + j0));
        float4 I2 = __ldcs((const float4*)(pI + 2*MS   + j0));
        float4 I3 = __ldcs((const float4*)(pI + 3*MS   + j0));
        float4 vjr = *(const float4*)&sjr_s[j0];
        float4 vji = *(const float4*)&sji_s[j0];
        float4 vcm = *(const float4*)&cm_s[j0];
        float4 vrs = *(const float4*)&rs_s[j0];

        float ar[4], ai[4];
        const float* jr = (const float*)&vjr;
        const float* ji = (const float*)&vji;
        const float* cm = (const float*)&vcm;
        const float* rs = (const float*)&vrs;
#pragma unroll
        for (int q = 0; q < 4; q++) {
            float scr = sri + jr[q];
            float sci = sii + ji[q];
            float pr = scr >= 0.f ? scr : apr * scr;
            float pi = sci >= 0.f ? sci : api * sci;
            float s2 = fmaf(pr, pr, pi * pi);
            float rm = rsqrtf(fmaxf(s2, 1e-36f));
            float mg = s2 * rm;
            float sc = __fdividef(__expf(mg - cm[q]) * rs[q], mg + 1e-12f);
            ar[q] = sc * pr;
            ai[q] = sc * pi;
        }
        const float* r0 = (const float*)&R0; const float* i0p = (const float*)&I0;
        const float* r1 = (const float*)&R1; const float* i1p = (const float*)&I1;
        const float* r2 = (const float*)&R2; const float* i2p = (const float*)&I2;
        const float* r3 = (const float*)&R3; const float* i3p = (const float*)&I3;
#pragma unroll
        for (int q = 0; q < 4; q++) {
            aR[0] = fmaf(r0[q], ar[q], fmaf(i0p[q], -ai[q], aR[0]));
            aI[0] = fmaf(r0[q], ai[q], fmaf(i0p[q],  ar[q], aI[0]));
            aR[1] = fmaf(r1[q], ar[q], fmaf(i1p[q], -ai[q], aR[1]));
            aI[1] = fmaf(r1[q], ai[q], fmaf(i1p[q],  ar[q], aI[1]));
            aR[2] = fmaf(r2[q], ar[q], fmaf(i2p[q], -ai[q], aR[2]));
            aI[2] = fmaf(r2[q], ai[q], fmaf(i2p[q],  ar[q], aI[2]));
            aR[3] = fmaf(r3[q], ar[q], fmaf(i3p[q], -ai[q], aR[3]));
            aI[3] = fmaf(r3[q], ai[q], fmaf(i3p[q],  ar[q], aI[3]));
        }
    }
#pragma unroll
    for (int off = 16; off; off >>= 1) {
#pragma unroll
        for (int m = 0; m < 4; m++) {
            aR[m] += __shfl_xor_sync(0xffffffffu, aR[m], off);
            aI[m] += __shfl_xor_sync(0xffffffffu, aI[m], off);
        }
    }
    if (lane == 0) {
        size_t o = (size_t)b * Mx * Nx + i;
#pragma unroll
        for (int m = 0; m < 4; m++) {
            g_rowR[o + m*Nx] = aR[m];
            g_rowI[o + m*Nx] = aI[m];
        }
    }
}

// ---------------- kernel D v4: fused output GEMM, 4x4 tiles -----------------
// Block: 128 threads (ty 0..7 row-groups x tx 0..15 out-groups), 32 rows x 64
// outs, per-thread 4x4 tile -> 32 FMAs per c-iter vs 4 LDS.128.
// SMEM: X transposed [c][row] stride 36; weights per-m [c][o] stride 68.
// 53KB dyn smem -> 4 blocks/SM, 16 warps/SM. Grid 256.
__global__ void __launch_bounds__(128) kD(const float* __restrict__ Xr,
                                          const float* __restrict__ Xi,
                                          const float* __restrict__ wr,
                                          const float* __restrict__ wi,
                                          float* __restrict__ out)
{
    extern __shared__ __align__(16) float sm[];
    float* Xr_s = sm;                    // [64][36]
    float* Xi_s = sm + 64*36;            // [64][36]
    float* wr_s = sm + 2*64*36;          // [64][68]
    float* wi_s = sm + 2*64*36 + 64*68;  // [64][68]

    int tid = threadIdx.x;
    int r0 = blockIdx.x << 5;            // 32 rows per block
    int b  = r0 >> 10;
    int jbase = r0 & 1023;

    // stage X tile transposed: 512 (row, cgroup) tasks over 128 threads
#pragma unroll
    for (int it = 0; it < 4; it++) {
        int idx = tid + (it << 7);       // 0..511
        int r  = idx >> 4;               // 0..31
        int cg = (idx & 15) << 2;        // 0..60
        float4 v = __ldg((const float4*)(Xr + (size_t)(r0 + r)*64 + cg));
        Xr_s[(cg+0)*36 + r] = v.x;
        Xr_s[(cg+1)*36 + r] = v.y;
        Xr_s[(cg+2)*36 + r] = v.z;
        Xr_s[(cg+3)*36 + r] = v.w;
        float4 u = __ldg((const float4*)(Xi + (size_t)(r0 + r)*64 + cg));
        Xi_s[(cg+0)*36 + r] = u.x;
        Xi_s[(cg+1)*36 + r] = u.y;
        Xi_s[(cg+2)*36 + r] = u.z;
        Xi_s[(cg+3)*36 + r] = u.w;
    }

    int tx = tid & 15, ty = tid >> 4;    // tx: out-group, ty: row-group
    int oo = tx << 2;                    // outputs oo..oo+3
    int rr = ty << 2;                    // local rows rr..rr+3

    // combine scalars: 4 rows x 4 m
    float cR[Mx][4], cI[Mx][4];
#pragma unroll
    for (int m = 0; m < Mx; m++)
#pragma unroll
        for (int r = 0; r < 4; r++) {
            size_t o = (size_t)(b*Mx + m)*Nx + jbase + rr + r;
            cR[m][r] = g_rowR[o];
            cI[m][r] = g_rowI[o];
        }

    float aR[4][4], aI[4][4];
#pragma unroll
    for (int r = 0; r < 4; r++)
#pragma unroll
        for (int o = 0; o < 4; o++) { aR[r][o] = 0.f; aI[r][o] = 0.f; }

#pragma unroll 1
    for (int m = 0; m < Mx; m++) {
        __syncthreads();                 // previous phase done reading w_s
        {
            const float4* wrg = (const float4*)(wr + (size_t)m * 4096);
            const float4* wig = (const float4*)(wi + (size_t)m * 4096);
#pragma unroll
            for (int k = 0; k < 8; k++) {
                int idx = tid + (k << 7);      // 0..1023
                int c = idx >> 4, og = (idx & 15) << 2;
                *(float4*)&wr_s[c*68 + og] = __ldg(wrg + idx);
                *(float4*)&wi_s[c*68 + og] = __ldg(wig + idx);
            }
        }
        __syncthreads();

        float pR[4][4], pI[4][4];
#pragma unroll
        for (int r = 0; r < 4; r++)
#pragma unroll
            for (int o = 0; o < 4; o++) { pR[r][o] = 0.f; pI[r][o] = 0.f; }

#pragma unroll 4
        for (int c = 0; c < 64; c++) {
            float4 xr4 = *(const float4*)&Xr_s[c*36 + rr];
            float4 xi4 = *(const float4*)&Xi_s[c*36 + rr];
            float4 wv  = *(const float4*)&wr_s[c*68 + oo];
            float4 vv  = *(const float4*)&wi_s[c*68 + oo];
            float xa[4] = {xr4.x, xr4.y, xr4.z, xr4.w};
            float ya[4] = {xi4.x, xi4.y, xi4.z, xi4.w};
            float wa[4] = {wv.x,  wv.y,  wv.z,  wv.w};
            float va[4] = {vv.x,  vv.y,  vv.z,  vv.w};
#pragma unroll
            for (int r = 0; r < 4; r++)
#pragma unroll
                for (int o = 0; o < 4; o++) {
                    pR[r][o] = fmaf(xa[r], wa[o], pR[r][o]);
                    pI[r][o] = fmaf(ya[r], va[o], pI[r][o]);
                }
        }
#pragma unroll
        for (int r = 0; r < 4; r++)
#pragma unroll
            for (int o = 0; o < 4; o++) {
                aR[r][o] = fmaf(cR[m][r], pR[r][o], fmaf(-cI[m][r], pI[r][o], aR[r][o]));
                aI[r][o] = fmaf(cI[m][r], pR[r][o], fmaf( cR[m][r], pI[r][o], aI[r][o]));
            }
    }

#pragma unroll
    for (int r = 0; r < 4; r++) {
        size_t row = (size_t)(r0 + rr + r);
        float4 vr = make_float4(aR[r][0], aR[r][1], aR[r][2], aR[r][3]);
        float4 vi = make_float4(aI[r][0], aI[r][1], aI[r][2], aI[r][3]);
        *(float4*)(out + row*64 + oo)               = vr;   // real block
        *(float4*)(out + (size_t)BNO + row*64 + oo) = vi;   // imag block
    }
}

// ---------------- launch ----------------------------------------------------
extern "C" void kernel_launch(void* const* d_in, const int* in_sizes, int n_in,
                              void* d_out, int out_size)
{
    const float* Xr  = (const float*)d_in[0];
    const float* Xi  = (const float*)d_in[1];
    const float* Lr  = (const float*)d_in[2];
    const float* Li  = (const float*)d_in[3];
    const float* wr  = (const float*)d_in[4];
    const float* wi  = (const float*)d_in[5];
    const float* awr = (const float*)d_in[6];
    const float* awi = (const float*)d_in[7];
    const float* abr = (const float*)d_in[8];
    const float* abi = (const float*)d_in[9];
    const float* par = (const float*)d_in[10];
    const float* pai = (const float*)d_in[11];
    float* out = (float*)d_out;

    const int KD_SMEM = (2*64*36 + 2*64*68) * 4;   // 53248 bytes
    static int attr_done = 0;
    if (!attr_done) {
        cudaFuncSetAttribute(kD, cudaFuncAttributeMaxDynamicSharedMemorySize, KD_SMEM);
        attr_done = 1;
    }

    kA<<<BN/8, 256>>>(Xr, Xi, awr, awi);
    kB<<<Bx*256, 256>>>(abr, abi, par, pai);
    kC<<<Bx*128, 256>>>(Lr, Li, abr, abi, par, pai);
    kD<<<BN/32, 128, KD_SMEM>>>(Xr, Xi, wr, wi, out);
}